// round 13
// baseline (speedup 1.0000x reference)
#include <cuda_runtime.h>
#include <math.h>

// ---------------------------------------------------------------------------
// Problem constants
// ---------------------------------------------------------------------------
#define B_     8
#define N_     2048
#define M_     32768
#define QD_    512
#define DR_    256
#define D_     512
#define H_     8
#define DH_    64
#define INNER_ 512
#define TOPK_  8
#define SCALE_ 0.125f

#define NB 128            // persistent blocks
#define NT 256            // threads per block
#define CHUNKS_PER_B 128  // 256 rows per chunk
#define NCAND (CHUNKS_PER_B * TOPK_)   // 1024
#define SUBS 16           // scan blocks per batch
#define STR 68            // smem tile stride (fused phase)

// ---------------------------------------------------------------------------
// Scratch
// ---------------------------------------------------------------------------
__device__ float g_e0[B_ * DR_];
__device__ float g_cand_d2[B_ * NCAND];
__device__ int   g_cand_idx[B_ * NCAND];
__device__ int   g_topk_idx[B_ * TOPK_];
__device__ float g_WqT[QD_ * INNER_];     // WqT[i][p] = Wq[p][i]
__device__ float g_kappa[B_ * QD_ * 64];  // [b][p][c], c=j*8+h (SCALE folded)
__device__ float g_vw[B_ * 64 * INNER_];  // [b][c][o]
__device__ unsigned int g_done[B_];       // per-batch scan counter
__device__ unsigned int g_count;          // grid barrier counter
__device__ volatile unsigned int g_gen;   // grid barrier generation

// ---------------------------------------------------------------------------
// helpers
// ---------------------------------------------------------------------------
__device__ __forceinline__ unsigned long long splat2(float f) {
    unsigned long long r;
    asm("mov.b64 %0, {%1, %1};" : "=l"(r) : "f"(f));
    return r;
}
__device__ __forceinline__ void fma2(unsigned long long& d,
                                     unsigned long long a,
                                     unsigned long long b) {
    asm("fma.rn.f32x2 %0, %1, %2, %0;" : "+l"(d) : "l"(a), "l"(b));
}
__device__ __forceinline__ float2 unpack2(unsigned long long v) {
    float2 r;
    asm("mov.b64 {%0, %1}, %2;" : "=f"(r.x), "=f"(r.y) : "l"(v));
    return r;
}
__device__ __forceinline__ unsigned long long u64min(unsigned long long a,
                                                     unsigned long long b) {
    return a < b ? a : b;
}

// grid-wide barrier (all NB blocks resident in wave 1 -> deadlock-free)
__device__ __forceinline__ void grid_sync(unsigned int target) {
    __syncthreads();
    if (threadIdx.x == 0) {
        __threadfence();
        unsigned int old = atomicAdd(&g_count, 1u);
        if (old == NB - 1) {
            g_count = 0;
            __threadfence();
            g_gen = target;
        } else {
            while (g_gen != target) {}
            __threadfence();
        }
    }
    __syncthreads();
}

// ---------------------------------------------------------------------------
// THE kernel: everything in one launch.
// ---------------------------------------------------------------------------
__global__ void __launch_bounds__(NT)
mega_kernel(const float* __restrict__ x,
            const float* __restrict__ ctx,
            const float* __restrict__ Wq,
            const float* __restrict__ We,
            const float* __restrict__ Wk,
            const float* __restrict__ Wv,
            const float* __restrict__ Wout,
            const float* __restrict__ bout,
            float* __restrict__ out) {
    extern __shared__ float fsm[];
    int bid = blockIdx.x;
    int tid = threadIdx.x;
    int warp = tid >> 5, lane = tid & 31;

    unsigned int gen0 = g_gen;  // read BEFORE this block's first arrival

    // =====================================================================
    // P0: blocks 0-7: e0[b] = (x[b,0,:]@Wq)@We ; blocks 8-127: transpose Wq
    // =====================================================================
    if (bid < 8) {
        int b = bid;
        float* xs = fsm;          // 512
        float* q0 = fsm + 512;    // 512
        xs[tid]       = x[(long)b * N_ * QD_ + tid];
        xs[tid + 256] = x[(long)b * N_ * QD_ + tid + 256];
        __syncthreads();
        float a0 = 0.f, a1 = 0.f;
#pragma unroll 8
        for (int c = 0; c < QD_; c++) {
            float xv = xs[c];
            a0 += xv * Wq[c * INNER_ + tid];
            a1 += xv * Wq[c * INNER_ + tid + 256];
        }
        q0[tid] = a0;
        q0[tid + 256] = a1;
        __syncthreads();
        float acc = 0.f;
#pragma unroll 8
        for (int c = 0; c < INNER_; c++)
            acc += q0[c] * We[c * DR_ + tid];
        g_e0[b * DR_ + tid] = acc;
    } else {
        // transpose: tiles t = bid-8, +120, +240
        float* tile = fsm;  // 32*33
        for (int t = bid - 8; t < 256; t += 120) {
            int bx = (t & 15) * 32, by = (t >> 4) * 32;
            int tx = tid & 31, ty = tid >> 5;
            __syncthreads();
#pragma unroll
            for (int r = ty; r < 32; r += 8)
                tile[r * 33 + tx] = Wq[(by + r) * 512 + bx + tx];
            __syncthreads();
#pragma unroll
            for (int r = ty; r < 32; r += 8)
                g_WqT[(bx + r) * 512 + by + tx] = tile[tx * 33 + r];
        }
    }

    grid_sync(gen0 + 1);

    // =====================================================================
    // P1: distance scan (16 blocks per b, 8 chunks each) + per-b merge
    // =====================================================================
    {
        int b = bid >> 4, sub = bid & 15;
        float* es = fsm;                       // 256
        float* s_d2 = fsm + 256;               // 64
        int*   s_ix = (int*)(fsm + 320);       // 64
        __shared__ int s_flag;
        __shared__ unsigned long long warpmin[8];
        __shared__ unsigned long long winner;

        es[tid] = g_e0[b * DR_ + tid];
        __syncthreads();

        const float4* e4 = (const float4*)es;
        float4 ea = e4[lane];
        float4 eb = e4[lane + 32];

        for (int i = 0; i < 8; i++) {
            int chunk = sub * 8 + i;
            float best[TOPK_];
            int   bidx[TOPK_];
#pragma unroll
            for (int q = 0; q < TOPK_; q++) { best[q] = 3.0e38f; bidx[q] = -1; }

            int row0 = chunk * 256 + warp * 32;
#pragma unroll 4
            for (int r = 0; r < 32; r++) {
                int row = row0 + r;
                const float4* crow =
                    (const float4*)(ctx + ((long)b * M_ + row) * D_);
                float4 ca = crow[lane];
                float4 cb = crow[lane + 32];
                float dx, d2 = 0.f;
                dx = ca.x - ea.x; d2 += dx * dx;
                dx = ca.y - ea.y; d2 += dx * dx;
                dx = ca.z - ea.z; d2 += dx * dx;
                dx = ca.w - ea.w; d2 += dx * dx;
                dx = cb.x - eb.x; d2 += dx * dx;
                dx = cb.y - eb.y; d2 += dx * dx;
                dx = cb.z - eb.z; d2 += dx * dx;
                dx = cb.w - eb.w; d2 += dx * dx;
#pragma unroll
                for (int off = 16; off; off >>= 1)
                    d2 += __shfl_down_sync(0xffffffffu, d2, off);
                if (lane == 0 && d2 < best[TOPK_ - 1]) {
                    int p = TOPK_ - 1;
                    while (p > 0 && best[p - 1] > d2) {
                        best[p] = best[p - 1]; bidx[p] = bidx[p - 1]; p--;
                    }
                    best[p] = d2; bidx[p] = row;
                }
            }

            if (lane == 0) {
#pragma unroll
                for (int q = 0; q < TOPK_; q++) {
                    s_d2[warp * TOPK_ + q] = best[q];
                    s_ix[warp * TOPK_ + q] = bidx[q];
                }
            }
            __syncthreads();

            if (tid == 0) {
                float fb[TOPK_]; int fi[TOPK_];
#pragma unroll
                for (int q = 0; q < TOPK_; q++) { fb[q] = 3.0e38f; fi[q] = -1; }
                for (int w = 0; w < 8; w++)
                    for (int q = 0; q < TOPK_; q++) {
                        float d2 = s_d2[w * TOPK_ + q];
                        if (d2 < fb[TOPK_ - 1]) {
                            int ix = s_ix[w * TOPK_ + q];
                            int p = TOPK_ - 1;
                            while (p > 0 && fb[p - 1] > d2) {
                                fb[p] = fb[p - 1]; fi[p] = fi[p - 1]; p--;
                            }
                            fb[p] = d2; fi[p] = ix;
                        }
                    }
                int off = (b * CHUNKS_PER_B + chunk) * TOPK_;
                for (int q = 0; q < TOPK_; q++) {
                    g_cand_d2[off + q] = fb[q];
                    g_cand_idx[off + q] = fi[q];
                }
            }
            __syncthreads();
        }

        // per-b last-block merge
        if (tid == 0) {
            __threadfence();
            unsigned int v = atomicAdd(&g_done[b], 1u);
            s_flag = (v == SUBS - 1);
        }
        __syncthreads();

        if (s_flag) {
            __threadfence();
            unsigned long long k[4];
            int base = b * NCAND;
#pragma unroll
            for (int s = 0; s < 4; s++) {
                int i = tid + s * 256;
                float d2 = g_cand_d2[base + i];
                int ix = g_cand_idx[base + i];
                k[s] = ((unsigned long long)__float_as_uint(d2) << 32) |
                       (unsigned int)ix;
            }
            for (int sel = 0; sel < TOPK_; sel++) {
                unsigned long long m =
                    u64min(u64min(k[0], k[1]), u64min(k[2], k[3]));
#pragma unroll
                for (int off = 16; off; off >>= 1)
                    m = u64min(m, __shfl_down_sync(0xffffffffu, m, off));
                if (lane == 0) warpmin[warp] = m;
                __syncthreads();
                if (tid == 0) {
                    unsigned long long w = warpmin[0];
#pragma unroll
                    for (int i = 1; i < 8; i++) w = u64min(w, warpmin[i]);
                    winner = w;
                    g_topk_idx[b * TOPK_ + sel] =
                        (int)(unsigned int)(w & 0xffffffffu);
                }
                __syncthreads();
                unsigned long long w = winner;
#pragma unroll
                for (int s = 0; s < 4; s++)
                    if (k[s] == w) k[s] = ~0ULL;
                __syncthreads();
            }
            if (tid == 0) g_done[b] = 0;  // reset for next replay
        }
    }

    grid_sync(gen0 + 2);

    // =====================================================================
    // P2: kv + kappa + vw.  task = (b, h, half): 8*8*2 = 128 blocks.
    // khat/vhat stay in smem (no global round trip).
    // =====================================================================
    {
        int b = bid >> 4;
        int h = (bid >> 1) & 7;
        int half = bid & 1;

        float* rows = fsm;          // 8*512 = 4096
        float* kh   = fsm + 4096;   // 8*64  = 512
        float* vh   = fsm + 4608;   // 8*64  = 512

#pragma unroll
        for (int j = 0; j < 8; j++) {
            int row = g_topk_idx[b * 8 + j];
            const float* crow = ctx + ((long)b * M_ + row) * D_;
            rows[j * 512 + tid]       = crow[tid];
            rows[j * 512 + 256 + tid] = crow[256 + tid];
        }
        __syncthreads();

        // khat/vhat for this h: thread = (j = tid>>5, dd = tid&31), d = dd, dd+32
        {
            int j = tid >> 5, dd = tid & 31;
            const float* lab = rows + j * 512 + 256;
            const float* rep = rows + j * 512;
            float k0 = 0.f, k1 = 0.f, v0 = 0.f, v1 = 0.f;
            int c0 = h * 64 + dd;
#pragma unroll 4
            for (int r = 0; r < DR_; r++) {
                float l = lab[r], rr = rep[r];
                k0 += l * Wk[r * INNER_ + c0];
                k1 += l * Wk[r * INNER_ + c0 + 32];
                v0 += rr * Wv[r * INNER_ + c0];
                v1 += rr * Wv[r * INNER_ + c0 + 32];
            }
            kh[j * 64 + dd]      = k0;
            kh[j * 64 + dd + 32] = k1;
            vh[j * 64 + dd]      = v0;
            vh[j * 64 + dd + 32] = v1;
        }
        __syncthreads();

        int p = half * 256 + tid;
        // kappa
        {
            float acc[8];
#pragma unroll
            for (int j = 0; j < 8; j++) acc[j] = 0.f;
#pragma unroll 8
            for (int d = 0; d < 64; d++) {
                float w = g_WqT[(h * 64 + d) * 512 + p];
#pragma unroll
                for (int j = 0; j < 8; j++) acc[j] += w * kh[j * 64 + d];
            }
            long kbase = ((long)b * 512 + p) * 64 + h;
#pragma unroll
            for (int j = 0; j < 8; j++)
                g_kappa[kbase + j * 8] = acc[j] * SCALE_;
        }
        // vw
        {
            float acc[8];
#pragma unroll
            for (int j = 0; j < 8; j++) acc[j] = 0.f;
#pragma unroll 8
            for (int d = 0; d < 64; d++) {
                float w = Wout[(h * 64 + d) * 512 + p];
#pragma unroll
                for (int j = 0; j < 8; j++) acc[j] += vh[j * 64 + d] * w;
            }
#pragma unroll
            for (int j = 0; j < 8; j++)
                g_vw[((long)b * 64 + j * 8 + h) * 512 + p] = acc[j];
        }
    }

    grid_sync(gen0 + 3);

    // =====================================================================
    // P3: fused sim + softmax + out  (task = (b = bid>>4, nc = bid&15))
    // =====================================================================
    {
        int nc = bid & 15, b = bid >> 4;
        int n0 = nc * 128;
        int ty = tid >> 4, tx = tid & 15;
        int tok0 = ty * 8;

        float* xs = fsm;              // 128*68
        float* ks = fsm + 128 * STR;  // 64*68

        const float* xb = x + ((long)b * N_ + n0) * QD_;
        const float* kb = g_kappa + (long)b * QD_ * 64;

        unsigned long long acc2[8][2];
#pragma unroll
        for (int t = 0; t < 8; t++) { acc2[t][0] = 0ULL; acc2[t][1] = 0ULL; }

        for (int pc = 0; pc < 8; pc++) {
            int p0 = pc * 64;
#pragma unroll
            for (int l = 0; l < 8; l++) {
                int f = tid + l * 256;
                int row = f >> 4, c4 = (f & 15) * 4;
                *(float4*)&xs[row * STR + c4] =
                    *(const float4*)(xb + (long)row * QD_ + p0 + c4);
            }
#pragma unroll
            for (int l = 0; l < 4; l++) {
                int f = tid + l * 256;
                int row = f >> 4, c4 = (f & 15) * 4;
                *(float4*)&ks[row * STR + c4] =
                    *(const float4*)(kb + (long)(p0 + row) * 64 + c4);
            }
            __syncthreads();

#pragma unroll
            for (int kk4 = 0; kk4 < 64; kk4 += 4) {
                float4 a4[8];
#pragma unroll
                for (int t = 0; t < 8; t++)
                    a4[t] = *(const float4*)&xs[(tok0 + t) * STR + kk4];
#pragma unroll
                for (int q = 0; q < 4; q++) {
                    ulonglong2 bp =
                        *(const ulonglong2*)&ks[(kk4 + q) * STR + tx * 4];
#pragma unroll
                    for (int t = 0; t < 8; t++) {
                        unsigned long long av =
                            splat2(((const float*)&a4[t])[q]);
                        fma2(acc2[t][0], av, bp.x);
                        fma2(acc2[t][1], av, bp.y);
                    }
                }
            }
            __syncthreads();
        }

#pragma unroll
        for (int t = 0; t < 8; t++) {
            float2 lo = unpack2(acc2[t][0]);
            float2 hi = unpack2(acc2[t][1]);
            *(float4*)&xs[(tok0 + t) * STR + tx * 4] =
                make_float4(lo.x, lo.y, hi.x, hi.y);
        }
        __syncthreads();

#pragma unroll
        for (int s = 0; s < 4; s++) {
            int task = s * 256 + tid;
            int t = task >> 3, h = task & 7;
            float v[8];
#pragma unroll
            for (int j = 0; j < 8; j++) v[j] = xs[t * STR + j * 8 + h];
            float m = v[0];
#pragma unroll
            for (int j = 1; j < 8; j++) m = fmaxf(m, v[j]);
            float e[8], sum = 0.f;
#pragma unroll
            for (int j = 0; j < 8; j++) { e[j] = __expf(v[j] - m); sum += e[j]; }
            float inv = 1.f / sum;
#pragma unroll
            for (int j = 0; j < 8; j++) xs[t * STR + j * 8 + h] = e[j] * inv;
        }
        __syncthreads();

        const float* vwb = g_vw + (long)b * 64 * 512;
        float* ob = out + ((long)b * N_ + n0) * 512;

        for (int oc = 0; oc < 8; oc++) {
            int o0 = oc * 64;
#pragma unroll
            for (int l = 0; l < 4; l++) {
                int f = tid + l * 256;
                int row = f >> 4, c4 = (f & 15) * 4;
                *(float4*)&ks[row * STR + c4] =
                    *(const float4*)(vwb + (long)row * 512 + o0 + c4);
            }
#pragma unroll
            for (int t = 0; t < 8; t++) { acc2[t][0] = 0ULL; acc2[t][1] = 0ULL; }
            __syncthreads();

#pragma unroll
            for (int cc4 = 0; cc4 < 64; cc4 += 4) {
                float4 a4[8];
#pragma unroll
                for (int t = 0; t < 8; t++)
                    a4[t] = *(const float4*)&xs[(tok0 + t) * STR + cc4];
#pragma unroll
                for (int q = 0; q < 4; q++) {
                    ulonglong2 bp =
                        *(const ulonglong2*)&ks[(cc4 + q) * STR + tx * 4];
#pragma unroll
                    for (int t = 0; t < 8; t++) {
                        unsigned long long av =
                            splat2(((const float*)&a4[t])[q]);
                        fma2(acc2[t][0], av, bp.x);
                        fma2(acc2[t][1], av, bp.y);
                    }
                }
            }

            float4 bias4 = *(const float4*)(bout + o0 + tx * 4);
#pragma unroll
            for (int t = 0; t < 8; t++) {
                float2 lo = unpack2(acc2[t][0]);
                float2 hi = unpack2(acc2[t][1]);
                float4 r = make_float4(lo.x + bias4.x, lo.y + bias4.y,
                                       hi.x + bias4.z, hi.y + bias4.w);
                *(float4*)(ob + (long)(tok0 + t) * 512 + o0 + tx * 4) = r;
            }
            __syncthreads();
        }
    }
}

// ---------------------------------------------------------------------------
// Launch: ONE kernel.
// ---------------------------------------------------------------------------
extern "C" void kernel_launch(void* const* d_in, const int* in_sizes, int n_in,
                              void* d_out, int out_size) {
    const float* x    = (const float*)d_in[0];
    const float* ctx  = (const float*)d_in[1];
    const float* Wq   = (const float*)d_in[2];
    const float* Wk   = (const float*)d_in[3];
    const float* Wv   = (const float*)d_in[4];
    const float* We   = (const float*)d_in[5];
    const float* Wout = (const float*)d_in[6];
    const float* bout = (const float*)d_in[7];
    float* out = (float*)d_out;

    const int SMEM = (128 * STR + 64 * STR) * sizeof(float);  // 52224 B
    static int configured = 0;
    cudaFuncSetAttribute(mega_kernel,
                         cudaFuncAttributeMaxDynamicSharedMemorySize, SMEM);
    (void)configured;

    mega_kernel<<<NB, NT, SMEM>>>(x, ctx, Wq, We, Wk, Wv, Wout, bout, out);
}

// round 14
// speedup vs baseline: 1.5405x; 1.5405x over previous
#include <cuda_runtime.h>
#include <math.h>

// ---------------------------------------------------------------------------
// Problem constants
// ---------------------------------------------------------------------------
#define B_     8
#define N_     2048
#define M_     32768
#define QD_    512
#define DR_    256
#define D_     512
#define H_     8
#define DH_    64
#define INNER_ 512
#define TOPK_  8
#define SCALE_ 0.125f

#define DIST_BLOCKS 128
#define NCAND (DIST_BLOCKS * TOPK_)   // 1024
#define STR 68

// ---------------------------------------------------------------------------
// Scratch
// ---------------------------------------------------------------------------
__device__ float g_e0[B_ * DR_];
__device__ float g_cand_d2[B_ * NCAND];
__device__ int   g_cand_idx[B_ * NCAND];
__device__ int   g_topk_idx[B_ * TOPK_];
__device__ float g_WqT[QD_ * INNER_];     // WqT[i][p] = Wq[p][i]
__device__ float g_kappa[B_ * QD_ * 64];  // [b][p][c], c=j*8+h (SCALE folded)
__device__ float g_vw[B_ * 64 * INNER_];  // [b][c][o]
__device__ unsigned int g_done[B_];       // per-batch scan counter

// ---------------------------------------------------------------------------
// helpers
// ---------------------------------------------------------------------------
__device__ __forceinline__ unsigned long long splat2(float f) {
    unsigned long long r;
    asm("mov.b64 %0, {%1, %1};" : "=l"(r) : "f"(f));
    return r;
}
__device__ __forceinline__ void fma2(unsigned long long& d,
                                     unsigned long long a,
                                     unsigned long long b) {
    asm("fma.rn.f32x2 %0, %1, %2, %0;" : "+l"(d) : "l"(a), "l"(b));
}
__device__ __forceinline__ float2 unpack2(unsigned long long v) {
    float2 r;
    asm("mov.b64 {%0, %1}, %2;" : "=f"(r.x), "=f"(r.y) : "l"(v));
    return r;
}
__device__ __forceinline__ unsigned long long u64min(unsigned long long a,
                                                     unsigned long long b) {
    return a < b ? a : b;
}

// ---------------------------------------------------------------------------
// Kernel 1: prep. blocks 0-7: e0[b] = (x[b,0,:]@Wq)@We (256 thr variant);
// blocks 8-127: transpose Wq into g_WqT (2-3 tiles each).
// ---------------------------------------------------------------------------
__global__ void __launch_bounds__(256)
prep_kernel(const float* __restrict__ x,
            const float* __restrict__ Wq,
            const float* __restrict__ We) {
    __shared__ float sm[1056];
    int bid = blockIdx.x;
    int tid = threadIdx.x;

    if (bid < 8) {
        int b = bid;
        float* xs = sm;          // 512
        float* q0 = sm + 512;    // 512
        xs[tid]       = x[(long)b * N_ * QD_ + tid];
        xs[tid + 256] = x[(long)b * N_ * QD_ + tid + 256];
        __syncthreads();
        float a0 = 0.f, a1 = 0.f;
#pragma unroll 8
        for (int c = 0; c < QD_; c++) {
            float xv = xs[c];
            a0 += xv * Wq[c * INNER_ + tid];
            a1 += xv * Wq[c * INNER_ + tid + 256];
        }
        q0[tid] = a0;
        q0[tid + 256] = a1;
        __syncthreads();
        float acc = 0.f;
#pragma unroll 8
        for (int c = 0; c < INNER_; c++)
            acc += q0[c] * We[c * DR_ + tid];
        g_e0[b * DR_ + tid] = acc;
    } else {
        float* tile = sm;  // 32*33
        for (int t = bid - 8; t < 256; t += 120) {
            int bx = (t & 15) * 32, by = (t >> 4) * 32;
            int tx = tid & 31, ty = tid >> 5;
            __syncthreads();
#pragma unroll
            for (int r = ty; r < 32; r += 8)
                tile[r * 33 + tx] = Wq[(by + r) * 512 + bx + tx];
            __syncthreads();
#pragma unroll
            for (int r = ty; r < 32; r += 8)
                g_WqT[(bx + r) * 512 + by + tx] = tile[tx * 33 + r];
        }
    }
}

// ---------------------------------------------------------------------------
// Kernel 2: distance scan + local top-8 + LAST-BLOCK global merge.
// grid (DIST_BLOCKS, B), 256 thr.   (identical to R12)
// ---------------------------------------------------------------------------
__global__ void dist_topk_kernel(const float* __restrict__ ctx) {
    int b = blockIdx.y;
    int chunk = blockIdx.x;
    int tid = threadIdx.x;
    int warp = tid >> 5, lane = tid & 31;

    __shared__ float es[DR_];
    __shared__ float s_d2[8][TOPK_];
    __shared__ int   s_ix[8][TOPK_];
    __shared__ int   s_last;

    if (tid < DR_) es[tid] = g_e0[b * DR_ + tid];
    __syncthreads();

    const float4* e4 = (const float4*)es;
    float4 ea = e4[lane];
    float4 eb = e4[lane + 32];

    float best[TOPK_];
    int   bidx[TOPK_];
#pragma unroll
    for (int i = 0; i < TOPK_; i++) { best[i] = 3.0e38f; bidx[i] = -1; }

    int row0 = chunk * 256 + warp * 32;
#pragma unroll 2
    for (int r = 0; r < 32; r++) {
        int row = row0 + r;
        const float4* crow = (const float4*)(ctx + ((long)b * M_ + row) * D_);
        float4 ca = crow[lane];
        float4 cb = crow[lane + 32];
        float dx, d2 = 0.f;
        dx = ca.x - ea.x; d2 += dx * dx;
        dx = ca.y - ea.y; d2 += dx * dx;
        dx = ca.z - ea.z; d2 += dx * dx;
        dx = ca.w - ea.w; d2 += dx * dx;
        dx = cb.x - eb.x; d2 += dx * dx;
        dx = cb.y - eb.y; d2 += dx * dx;
        dx = cb.z - eb.z; d2 += dx * dx;
        dx = cb.w - eb.w; d2 += dx * dx;
#pragma unroll
        for (int off = 16; off; off >>= 1)
            d2 += __shfl_down_sync(0xffffffffu, d2, off);
        if (lane == 0 && d2 < best[TOPK_ - 1]) {
            int p = TOPK_ - 1;
            while (p > 0 && best[p - 1] > d2) {
                best[p] = best[p - 1]; bidx[p] = bidx[p - 1]; p--;
            }
            best[p] = d2; bidx[p] = row;
        }
    }

    if (lane == 0) {
#pragma unroll
        for (int i = 0; i < TOPK_; i++) { s_d2[warp][i] = best[i]; s_ix[warp][i] = bidx[i]; }
    }
    __syncthreads();

    if (tid == 0) {
        float fb[TOPK_]; int fi[TOPK_];
#pragma unroll
        for (int i = 0; i < TOPK_; i++) { fb[i] = 3.0e38f; fi[i] = -1; }
        for (int w = 0; w < 8; w++)
            for (int i = 0; i < TOPK_; i++) {
                float d2 = s_d2[w][i];
                if (d2 < fb[TOPK_ - 1]) {
                    int ix = s_ix[w][i];
                    int p = TOPK_ - 1;
                    while (p > 0 && fb[p - 1] > d2) {
                        fb[p] = fb[p - 1]; fi[p] = fi[p - 1]; p--;
                    }
                    fb[p] = d2; fi[p] = ix;
                }
            }
        int off = (b * DIST_BLOCKS + chunk) * TOPK_;
        for (int i = 0; i < TOPK_; i++) { g_cand_d2[off + i] = fb[i]; g_cand_idx[off + i] = fi[i]; }
        __threadfence();
        unsigned int v = atomicAdd(&g_done[b], 1u);
        s_last = (v == DIST_BLOCKS - 1);
    }
    __syncthreads();

    if (!s_last) return;
    __threadfence();  // acquire

    __shared__ unsigned long long warpmin[8];
    __shared__ unsigned long long winner;

    unsigned long long k[4];
    int base = b * NCAND;
#pragma unroll
    for (int s = 0; s < 4; s++) {
        int i = tid + s * 256;
        float d2 = g_cand_d2[base + i];
        int ix = g_cand_idx[base + i];
        k[s] = ((unsigned long long)__float_as_uint(d2) << 32) | (unsigned int)ix;
    }

    for (int sel = 0; sel < TOPK_; sel++) {
        unsigned long long m = u64min(u64min(k[0], k[1]), u64min(k[2], k[3]));
#pragma unroll
        for (int off = 16; off; off >>= 1)
            m = u64min(m, __shfl_down_sync(0xffffffffu, m, off));
        if (lane == 0) warpmin[warp] = m;
        __syncthreads();
        if (tid == 0) {
            unsigned long long w = warpmin[0];
#pragma unroll
            for (int i = 1; i < 8; i++) w = u64min(w, warpmin[i]);
            winner = w;
            g_topk_idx[b * TOPK_ + sel] = (int)(unsigned int)(w & 0xffffffffu);
        }
        __syncthreads();
        unsigned long long w = winner;
#pragma unroll
        for (int s = 0; s < 4; s++)
            if (k[s] == w) k[s] = ~0ULL;
        __syncthreads();
    }
    if (tid == 0) g_done[b] = 0;  // reset for graph replay
}

// ---------------------------------------------------------------------------
// Kernel 3: kv + kappa + vw in one pass. grid 128 = (b, h, half), 256 thr.
// khat/vhat computed into smem, no global round trip. (R13-P2 standalone)
// ---------------------------------------------------------------------------
__global__ void __launch_bounds__(256)
kvkw_kernel(const float* __restrict__ ctx,
            const float* __restrict__ Wk,
            const float* __restrict__ Wv,
            const float* __restrict__ Wout) {
    __shared__ float rows[8 * 512];
    __shared__ float kh[8 * 64];
    __shared__ float vh[8 * 64];

    int bid = blockIdx.x;
    int b = bid >> 4;
    int h = (bid >> 1) & 7;
    int half = bid & 1;
    int tid = threadIdx.x;  // 256

#pragma unroll
    for (int j = 0; j < 8; j++) {
        int row = g_topk_idx[b * 8 + j];
        const float* crow = ctx + ((long)b * M_ + row) * D_;
        rows[j * 512 + tid]       = crow[tid];
        rows[j * 512 + 256 + tid] = crow[256 + tid];
    }
    __syncthreads();

    // khat/vhat for this h: thread = (j = tid>>5, dd = tid&31); d = dd, dd+32
    {
        int j = tid >> 5, dd = tid & 31;
        const float* lab = rows + j * 512 + 256;
        const float* rep = rows + j * 512;
        float k0 = 0.f, k1 = 0.f, v0 = 0.f, v1 = 0.f;
        int c0 = h * 64 + dd;
#pragma unroll 4
        for (int r = 0; r < DR_; r++) {
            float l = lab[r], rr = rep[r];
            k0 += l * Wk[r * INNER_ + c0];
            k1 += l * Wk[r * INNER_ + c0 + 32];
            v0 += rr * Wv[r * INNER_ + c0];
            v1 += rr * Wv[r * INNER_ + c0 + 32];
        }
        kh[j * 64 + dd]      = k0;
        kh[j * 64 + dd + 32] = k1;
        vh[j * 64 + dd]      = v0;
        vh[j * 64 + dd + 32] = v1;
    }
    __syncthreads();

    int p = half * 256 + tid;
    // kappa
    {
        float acc[8];
#pragma unroll
        for (int j = 0; j < 8; j++) acc[j] = 0.f;
#pragma unroll 8
        for (int d = 0; d < 64; d++) {
            float w = g_WqT[(h * 64 + d) * 512 + p];
#pragma unroll
            for (int j = 0; j < 8; j++) acc[j] += w * kh[j * 64 + d];
        }
        long kbase = ((long)b * 512 + p) * 64 + h;
#pragma unroll
        for (int j = 0; j < 8; j++)
            g_kappa[kbase + j * 8] = acc[j] * SCALE_;
    }
    // vw
    {
        float acc[8];
#pragma unroll
        for (int j = 0; j < 8; j++) acc[j] = 0.f;
#pragma unroll 8
        for (int d = 0; d < 64; d++) {
            float w = Wout[(h * 64 + d) * 512 + p];
#pragma unroll
            for (int j = 0; j < 8; j++) acc[j] += vh[j * 64 + d] * w;
        }
#pragma unroll
        for (int j = 0; j < 8; j++)
            g_vw[((long)b * 64 + j * 8 + h) * 512 + p] = acc[j];
    }
}

// ---------------------------------------------------------------------------
// Kernel 4: fused sim + softmax + out. f32x2 over column pairs.
// grid (16, B), 256 thr, single wave.  (identical to R12)
// ---------------------------------------------------------------------------
__global__ void __launch_bounds__(256)
fused_attn(const float* __restrict__ x,
           float* __restrict__ out,
           const float* __restrict__ bout) {
    extern __shared__ float fsm[];
    float* xs = fsm;              // 128*68
    float* ks = fsm + 128 * STR;  // 64*68

    int nc = blockIdx.x, b = blockIdx.y;
    int n0 = nc * 128;
    int tid = threadIdx.x;
    int ty = tid >> 4, tx = tid & 15;
    int tok0 = ty * 8;

    const float* xb = x + ((long)b * N_ + n0) * QD_;
    const float* kb = g_kappa + (long)b * QD_ * 64;

    unsigned long long acc2[8][2];
#pragma unroll
    for (int t = 0; t < 8; t++) { acc2[t][0] = 0ULL; acc2[t][1] = 0ULL; }

    for (int pc = 0; pc < 8; pc++) {
        int p0 = pc * 64;
#pragma unroll
        for (int l = 0; l < 8; l++) {
            int f = tid + l * 256;
            int row = f >> 4, c4 = (f & 15) * 4;
            *(float4*)&xs[row * STR + c4] =
                *(const float4*)(xb + (long)row * QD_ + p0 + c4);
        }
#pragma unroll
        for (int l = 0; l < 4; l++) {
            int f = tid + l * 256;
            int row = f >> 4, c4 = (f & 15) * 4;
            *(float4*)&ks[row * STR + c4] =
                *(const float4*)(kb + (long)(p0 + row) * 64 + c4);
        }
        __syncthreads();

#pragma unroll
        for (int kk4 = 0; kk4 < 64; kk4 += 4) {
            float4 a4[8];
#pragma unroll
            for (int t = 0; t < 8; t++)
                a4[t] = *(const float4*)&xs[(tok0 + t) * STR + kk4];
#pragma unroll
            for (int q = 0; q < 4; q++) {
                ulonglong2 bp = *(const ulonglong2*)&ks[(kk4 + q) * STR + tx * 4];
#pragma unroll
                for (int t = 0; t < 8; t++) {
                    unsigned long long av = splat2(((const float*)&a4[t])[q]);
                    fma2(acc2[t][0], av, bp.x);
                    fma2(acc2[t][1], av, bp.y);
                }
            }
        }
        __syncthreads();
    }

#pragma unroll
    for (int t = 0; t < 8; t++) {
        float2 lo = unpack2(acc2[t][0]);
        float2 hi = unpack2(acc2[t][1]);
        *(float4*)&xs[(tok0 + t) * STR + tx * 4] =
            make_float4(lo.x, lo.y, hi.x, hi.y);
    }
    __syncthreads();

#pragma unroll
    for (int s = 0; s < 4; s++) {
        int task = s * 256 + tid;
        int t = task >> 3, h = task & 7;
        float v[8];
#pragma unroll
        for (int j = 0; j < 8; j++) v[j] = xs[t * STR + j * 8 + h];
        float m = v[0];
#pragma unroll
        for (int j = 1; j < 8; j++) m = fmaxf(m, v[j]);
        float e[8], sum = 0.f;
#pragma unroll
        for (int j = 0; j < 8; j++) { e[j] = __expf(v[j] - m); sum += e[j]; }
        float inv = 1.f / sum;
#pragma unroll
        for (int j = 0; j < 8; j++) xs[t * STR + j * 8 + h] = e[j] * inv;
    }
    __syncthreads();

    const float* vwb = g_vw + (long)b * 64 * 512;
    float* ob = out + ((long)b * N_ + n0) * 512;

    for (int oc = 0; oc < 8; oc++) {
        int o0 = oc * 64;
#pragma unroll
        for (int l = 0; l < 4; l++) {
            int f = tid + l * 256;
            int row = f >> 4, c4 = (f & 15) * 4;
            *(float4*)&ks[row * STR + c4] =
                *(const float4*)(vwb + (long)row * 512 + o0 + c4);
        }
#pragma unroll
        for (int t = 0; t < 8; t++) { acc2[t][0] = 0ULL; acc2[t][1] = 0ULL; }
        __syncthreads();

#pragma unroll
        for (int cc4 = 0; cc4 < 64; cc4 += 4) {
            float4 a4[8];
#pragma unroll
            for (int t = 0; t < 8; t++)
                a4[t] = *(const float4*)&xs[(tok0 + t) * STR + cc4];
#pragma unroll
            for (int q = 0; q < 4; q++) {
                ulonglong2 bp = *(const ulonglong2*)&ks[(cc4 + q) * STR + tx * 4];
#pragma unroll
                for (int t = 0; t < 8; t++) {
                    unsigned long long av = splat2(((const float*)&a4[t])[q]);
                    fma2(acc2[t][0], av, bp.x);
                    fma2(acc2[t][1], av, bp.y);
                }
            }
        }

        float4 bias4 = *(const float4*)(bout + o0 + tx * 4);
#pragma unroll
        for (int t = 0; t < 8; t++) {
            float2 lo = unpack2(acc2[t][0]);
            float2 hi = unpack2(acc2[t][1]);
            float4 r = make_float4(lo.x + bias4.x, lo.y + bias4.y,
                                   hi.x + bias4.z, hi.y + bias4.w);
            *(float4*)(ob + (long)(tok0 + t) * 512 + o0 + tx * 4) = r;
        }
        __syncthreads();
    }
}

// ---------------------------------------------------------------------------
// Launch: 4 kernels.
// ---------------------------------------------------------------------------
extern "C" void kernel_launch(void* const* d_in, const int* in_sizes, int n_in,
                              void* d_out, int out_size) {
    const float* x    = (const float*)d_in[0];
    const float* ctx  = (const float*)d_in[1];
    const float* Wq   = (const float*)d_in[2];
    const float* Wk   = (const float*)d_in[3];
    const float* Wv   = (const float*)d_in[4];
    const float* We   = (const float*)d_in[5];
    const float* Wout = (const float*)d_in[6];
    const float* bout = (const float*)d_in[7];
    float* out = (float*)d_out;

    const int FA_SMEM = (128 * STR + 64 * STR) * sizeof(float);  // ~51 KB
    cudaFuncSetAttribute(fused_attn,
                         cudaFuncAttributeMaxDynamicSharedMemorySize, FA_SMEM);

    prep_kernel<<<128, 256>>>(x, Wq, We);
    dist_topk_kernel<<<dim3(DIST_BLOCKS, B_), 256>>>(ctx);
    kvkw_kernel<<<128, 256>>>(ctx, Wk, Wv, Wout);
    fused_attn<<<dim3(16, B_), 256, FA_SMEM>>>(x, out, bout);
}

// round 15
// speedup vs baseline: 2.0913x; 1.3575x over previous
#include <cuda_runtime.h>
#include <math.h>

// ---------------------------------------------------------------------------
// Problem constants
// ---------------------------------------------------------------------------
#define B_     8
#define N_     2048
#define M_     32768
#define QD_    512
#define DR_    256
#define D_     512
#define H_     8
#define DH_    64
#define INNER_ 512
#define TOPK_  8
#define SCALE_ 0.125f

#define DIST_BLOCKS 128
#define NCAND (DIST_BLOCKS * TOPK_)   // 1024
#define STR 68

// ---------------------------------------------------------------------------
// Scratch
// ---------------------------------------------------------------------------
__device__ float g_e0[B_ * DR_];
__device__ float g_cand_d2[B_ * NCAND];
__device__ int   g_cand_idx[B_ * NCAND];
__device__ int   g_topk_idx[B_ * TOPK_];
__device__ float g_WqT[QD_ * INNER_];     // WqT[i][p] = Wq[p][i]
__device__ float g_khat[B_ * 64 * 64];    // [b][c=j*8+h][d]
__device__ float g_vhat[B_ * 64 * 64];    // [b][c][d]
__device__ float g_kappa[B_ * QD_ * 64];  // [b][p][c], c=j*8+h (SCALE folded)
__device__ float g_vw[B_ * 64 * INNER_];  // [b][c][o]
__device__ unsigned int g_done[B_];       // per-batch scan counter

// ---------------------------------------------------------------------------
// helpers
// ---------------------------------------------------------------------------
__device__ __forceinline__ unsigned long long splat2(float f) {
    unsigned long long r;
    asm("mov.b64 %0, {%1, %1};" : "=l"(r) : "f"(f));
    return r;
}
__device__ __forceinline__ void fma2(unsigned long long& d,
                                     unsigned long long a,
                                     unsigned long long b) {
    asm("fma.rn.f32x2 %0, %1, %2, %0;" : "+l"(d) : "l"(a), "l"(b));
}
__device__ __forceinline__ float2 unpack2(unsigned long long v) {
    float2 r;
    asm("mov.b64 {%0, %1}, %2;" : "=f"(r.x), "=f"(r.y) : "l"(v));
    return r;
}
__device__ __forceinline__ unsigned long long u64min(unsigned long long a,
                                                     unsigned long long b) {
    return a < b ? a : b;
}

// ---------------------------------------------------------------------------
// Kernel 0: transpose Wq -> g_WqT  (R12)
// ---------------------------------------------------------------------------
__global__ void transpose512(const float* __restrict__ Wq) {
    __shared__ float tile[32][33];
    int bx = blockIdx.x * 32, by = blockIdx.y * 32;
    int tx = threadIdx.x & 31, ty = threadIdx.x >> 5;
#pragma unroll
    for (int r = ty; r < 32; r += 8)
        tile[r][tx] = Wq[(by + r) * 512 + bx + tx];
    __syncthreads();
#pragma unroll
    for (int r = ty; r < 32; r += 8)
        g_WqT[(bx + r) * 512 + by + tx] = tile[tx][r];
}

// ---------------------------------------------------------------------------
// Kernel 1: e0  (R12)
// ---------------------------------------------------------------------------
__global__ void e0_kernel(const float* __restrict__ x,
                          const float* __restrict__ Wq,
                          const float* __restrict__ We) {
    int b = blockIdx.x;
    int tid = threadIdx.x;  // 512
    __shared__ float xs[QD_];
    __shared__ float q0[QD_];
    __shared__ float part[512];

    xs[tid] = x[(long)b * N_ * QD_ + tid];
    __syncthreads();

    {
        float acc = 0.f;
#pragma unroll 16
        for (int c = 0; c < QD_; c++)
            acc += xs[c] * Wq[c * INNER_ + tid];
        q0[tid] = acc;
    }
    __syncthreads();

    {
        int half = tid >> 8;
        int o = tid & 255;
        int c0 = half * 256;
        float acc = 0.f;
#pragma unroll 16
        for (int c = 0; c < 256; c++)
            acc += q0[c0 + c] * We[(c0 + c) * DR_ + o];
        part[tid] = acc;
    }
    __syncthreads();
    if (tid < DR_)
        g_e0[b * DR_ + tid] = part[tid] + part[tid + 256];
}

// ---------------------------------------------------------------------------
// Kernel 2: distance scan + local top-8 + LAST-BLOCK merge (R12)
// ---------------------------------------------------------------------------
__global__ void dist_topk_kernel(const float* __restrict__ ctx) {
    int b = blockIdx.y;
    int chunk = blockIdx.x;
    int tid = threadIdx.x;
    int warp = tid >> 5, lane = tid & 31;

    __shared__ float es[DR_];
    __shared__ float s_d2[8][TOPK_];
    __shared__ int   s_ix[8][TOPK_];
    __shared__ int   s_last;

    if (tid < DR_) es[tid] = g_e0[b * DR_ + tid];
    __syncthreads();

    const float4* e4 = (const float4*)es;
    float4 ea = e4[lane];
    float4 eb = e4[lane + 32];

    float best[TOPK_];
    int   bidx[TOPK_];
#pragma unroll
    for (int i = 0; i < TOPK_; i++) { best[i] = 3.0e38f; bidx[i] = -1; }

    int row0 = chunk * 256 + warp * 32;
#pragma unroll 2
    for (int r = 0; r < 32; r++) {
        int row = row0 + r;
        const float4* crow = (const float4*)(ctx + ((long)b * M_ + row) * D_);
        float4 ca = crow[lane];
        float4 cb = crow[lane + 32];
        float dx, d2 = 0.f;
        dx = ca.x - ea.x; d2 += dx * dx;
        dx = ca.y - ea.y; d2 += dx * dx;
        dx = ca.z - ea.z; d2 += dx * dx;
        dx = ca.w - ea.w; d2 += dx * dx;
        dx = cb.x - eb.x; d2 += dx * dx;
        dx = cb.y - eb.y; d2 += dx * dx;
        dx = cb.z - eb.z; d2 += dx * dx;
        dx = cb.w - eb.w; d2 += dx * dx;
#pragma unroll
        for (int off = 16; off; off >>= 1)
            d2 += __shfl_down_sync(0xffffffffu, d2, off);
        if (lane == 0 && d2 < best[TOPK_ - 1]) {
            int p = TOPK_ - 1;
            while (p > 0 && best[p - 1] > d2) {
                best[p] = best[p - 1]; bidx[p] = bidx[p - 1]; p--;
            }
            best[p] = d2; bidx[p] = row;
        }
    }

    if (lane == 0) {
#pragma unroll
        for (int i = 0; i < TOPK_; i++) { s_d2[warp][i] = best[i]; s_ix[warp][i] = bidx[i]; }
    }
    __syncthreads();

    if (tid == 0) {
        float fb[TOPK_]; int fi[TOPK_];
#pragma unroll
        for (int i = 0; i < TOPK_; i++) { fb[i] = 3.0e38f; fi[i] = -1; }
        for (int w = 0; w < 8; w++)
            for (int i = 0; i < TOPK_; i++) {
                float d2 = s_d2[w][i];
                if (d2 < fb[TOPK_ - 1]) {
                    int ix = s_ix[w][i];
                    int p = TOPK_ - 1;
                    while (p > 0 && fb[p - 1] > d2) {
                        fb[p] = fb[p - 1]; fi[p] = fi[p - 1]; p--;
                    }
                    fb[p] = d2; fi[p] = ix;
                }
            }
        int off = (b * DIST_BLOCKS + chunk) * TOPK_;
        for (int i = 0; i < TOPK_; i++) { g_cand_d2[off + i] = fb[i]; g_cand_idx[off + i] = fi[i]; }
        __threadfence();
        unsigned int v = atomicAdd(&g_done[b], 1u);
        s_last = (v == DIST_BLOCKS - 1);
    }
    __syncthreads();

    if (!s_last) return;
    __threadfence();  // acquire

    __shared__ unsigned long long warpmin[8];
    __shared__ unsigned long long winner;

    unsigned long long k[4];
    int base = b * NCAND;
#pragma unroll
    for (int s = 0; s < 4; s++) {
        int i = tid + s * 256;
        float d2 = g_cand_d2[base + i];
        int ix = g_cand_idx[base + i];
        k[s] = ((unsigned long long)__float_as_uint(d2) << 32) | (unsigned int)ix;
    }

    for (int sel = 0; sel < TOPK_; sel++) {
        unsigned long long m = u64min(u64min(k[0], k[1]), u64min(k[2], k[3]));
#pragma unroll
        for (int off = 16; off; off >>= 1)
            m = u64min(m, __shfl_down_sync(0xffffffffu, m, off));
        if (lane == 0) warpmin[warp] = m;
        __syncthreads();
        if (tid == 0) {
            unsigned long long w = warpmin[0];
#pragma unroll
            for (int i = 1; i < 8; i++) w = u64min(w, warpmin[i]);
            winner = w;
            g_topk_idx[b * TOPK_ + sel] = (int)(unsigned int)(w & 0xffffffffu);
        }
        __syncthreads();
        unsigned long long w = winner;
#pragma unroll
        for (int s = 0; s < 4; s++)
            if (k[s] == w) k[s] = ~0ULL;
        __syncthreads();
    }
    if (tid == 0) g_done[b] = 0;  // reset for graph replay
}

// ---------------------------------------------------------------------------
// Kernel 3a: k/v vectors. grid 64, 1024 thr. (R12)
// ---------------------------------------------------------------------------
__global__ void __launch_bounds__(1024)
kvA_kernel(const float* __restrict__ ctx,
           const float* __restrict__ Wk,
           const float* __restrict__ Wv) {
    int bj = blockIdx.x;
    int b = bj >> 3, j = bj & 7;
    int tid = threadIdx.x;  // 1024

    __shared__ float reps[DR_];
    __shared__ float labels[DR_];

    int row = g_topk_idx[bj];
    const float* crow = ctx + ((long)b * M_ + row) * D_;
    if (tid < 256)      reps[tid] = crow[tid];
    else if (tid < 512) labels[tid - 256] = crow[tid];
    __syncthreads();

    int col = tid & 511;
    bool isK = tid < 512;
    const float* W   = isK ? Wk : Wv;
    const float* vec = isK ? labels : reps;

    float acc = 0.f;
#pragma unroll 16
    for (int r = 0; r < DR_; r++)
        acc += vec[r] * W[r * INNER_ + col];

    int h = col >> 6, d = col & 63;
    long dst = ((long)b * 64 + j * 8 + h) * 64 + d;
    if (isK) g_khat[dst] = acc;
    else     g_vhat[dst] = acc;
}

// ---------------------------------------------------------------------------
// Kernel 3b: kappa + vw. grid (8 h, 8 b), 512 thr. (R12)
// ---------------------------------------------------------------------------
__global__ void __launch_bounds__(512)
kwB_kernel(const float* __restrict__ Wout) {
    int h = blockIdx.x, b = blockIdx.y;
    int tid = threadIdx.x;  // 512 -> p / o

    __shared__ float kh[8][64];
    __shared__ float vh[8][64];
    {
        int j = tid >> 6, d = tid & 63;
        long src = ((long)b * 64 + j * 8 + h) * 64 + d;
        kh[j][d] = g_khat[src];
        vh[j][d] = g_vhat[src];
    }
    __syncthreads();

    {
        float acc[8];
#pragma unroll
        for (int j = 0; j < 8; j++) acc[j] = 0.f;
#pragma unroll 8
        for (int d = 0; d < 64; d++) {
            float w = g_WqT[(h * 64 + d) * 512 + tid];
#pragma unroll
            for (int j = 0; j < 8; j++) acc[j] += w * kh[j][d];
        }
        long kbase = ((long)b * 512 + tid) * 64 + h;
#pragma unroll
        for (int j = 0; j < 8; j++) g_kappa[kbase + j * 8] = acc[j] * SCALE_;
    }

    {
        float acc[8];
#pragma unroll
        for (int j = 0; j < 8; j++) acc[j] = 0.f;
#pragma unroll 8
        for (int d = 0; d < 64; d++) {
            float w = Wout[(h * 64 + d) * 512 + tid];
#pragma unroll
            for (int j = 0; j < 8; j++) acc[j] += vh[j][d] * w;
        }
#pragma unroll
        for (int j = 0; j < 8; j++)
            g_vw[((long)b * 64 + j * 8 + h) * 512 + tid] = acc[j];
    }
}

// ---------------------------------------------------------------------------
// Kernel 4: fused sim + softmax + out. 64-token tiles, grid (32, B) = 256
// blocks, static smem ~34 KB -> 2 blocks/SM (occ 25%). f32x2 column pairs.
// ---------------------------------------------------------------------------
__global__ void __launch_bounds__(256)
fused_attn(const float* __restrict__ x,
           float* __restrict__ out,
           const float* __restrict__ bout) {
    __shared__ float xs[64 * STR];   // x chunk, then attention weights a
    __shared__ float ks[64 * STR];   // kappa chunk, then vw chunk

    int nc = blockIdx.x, b = blockIdx.y;
    int n0 = nc * 64;
    int tid = threadIdx.x;
    int ty = tid >> 4, tx = tid & 15;  // 4 tokens x (4 cols = 2 pairs)
    int tok0 = ty * 4;

    const float* xb = x + ((long)b * N_ + n0) * QD_;
    const float* kb = g_kappa + (long)b * QD_ * 64;

    unsigned long long acc2[4][2];
#pragma unroll
    for (int t = 0; t < 4; t++) { acc2[t][0] = 0ULL; acc2[t][1] = 0ULL; }

    // ---- phase 1: sim = x @ kappa, K in 8 chunks of 64 ----
    for (int pc = 0; pc < 8; pc++) {
        int p0 = pc * 64;
#pragma unroll
        for (int l = 0; l < 4; l++) {
            int f = tid + l * 256;
            int row = f >> 4, c4 = (f & 15) * 4;
            *(float4*)&xs[row * STR + c4] =
                *(const float4*)(xb + (long)row * QD_ + p0 + c4);
            *(float4*)&ks[row * STR + c4] =
                *(const float4*)(kb + (long)(p0 + row) * 64 + c4);
        }
        __syncthreads();

#pragma unroll
        for (int kk4 = 0; kk4 < 64; kk4 += 4) {
            float4 a4[4];
#pragma unroll
            for (int t = 0; t < 4; t++)
                a4[t] = *(const float4*)&xs[(tok0 + t) * STR + kk4];
#pragma unroll
            for (int q = 0; q < 4; q++) {
                ulonglong2 bp = *(const ulonglong2*)&ks[(kk4 + q) * STR + tx * 4];
#pragma unroll
                for (int t = 0; t < 4; t++) {
                    unsigned long long av = splat2(((const float*)&a4[t])[q]);
                    fma2(acc2[t][0], av, bp.x);
                    fma2(acc2[t][1], av, bp.y);
                }
            }
        }
        __syncthreads();
    }

    // ---- dump sim into xs[token][c] ----
#pragma unroll
    for (int t = 0; t < 4; t++) {
        float2 lo = unpack2(acc2[t][0]);
        float2 hi = unpack2(acc2[t][1]);
        *(float4*)&xs[(tok0 + t) * STR + tx * 4] =
            make_float4(lo.x, lo.y, hi.x, hi.y);
    }
    __syncthreads();

    // ---- softmax in place over j per (token, head): 512 tasks ----
#pragma unroll
    for (int s = 0; s < 2; s++) {
        int task = s * 256 + tid;
        int t = task >> 3, h = task & 7;
        float v[8];
#pragma unroll
        for (int j = 0; j < 8; j++) v[j] = xs[t * STR + j * 8 + h];
        float m = v[0];
#pragma unroll
        for (int j = 1; j < 8; j++) m = fmaxf(m, v[j]);
        float e[8], sum = 0.f;
#pragma unroll
        for (int j = 0; j < 8; j++) { e[j] = __expf(v[j] - m); sum += e[j]; }
        float inv = 1.f / sum;
#pragma unroll
        for (int j = 0; j < 8; j++) xs[t * STR + j * 8 + h] = e[j] * inv;
    }
    __syncthreads();

    // ---- phase 3: out = a @ vw + bias, 8 o-chunks of 64 ----
    const float* vwb = g_vw + (long)b * 64 * 512;
    float* ob = out + ((long)b * N_ + n0) * 512;

    for (int oc = 0; oc < 8; oc++) {
        int o0 = oc * 64;
#pragma unroll
        for (int l = 0; l < 4; l++) {
            int f = tid + l * 256;
            int row = f >> 4, c4 = (f & 15) * 4;
            *(float4*)&ks[row * STR + c4] =
                *(const float4*)(vwb + (long)row * 512 + o0 + c4);
        }
#pragma unroll
        for (int t = 0; t < 4; t++) { acc2[t][0] = 0ULL; acc2[t][1] = 0ULL; }
        __syncthreads();

#pragma unroll
        for (int cc4 = 0; cc4 < 64; cc4 += 4) {
            float4 a4[4];
#pragma unroll
            for (int t = 0; t < 4; t++)
                a4[t] = *(const float4*)&xs[(tok0 + t) * STR + cc4];
#pragma unroll
            for (int q = 0; q < 4; q++) {
                ulonglong2 bp = *(const ulonglong2*)&ks[(cc4 + q) * STR + tx * 4];
#pragma unroll
                for (int t = 0; t < 4; t++) {
                    unsigned long long av = splat2(((const float*)&a4[t])[q]);
                    fma2(acc2[t][0], av, bp.x);
                    fma2(acc2[t][1], av, bp.y);
                }
            }
        }

        float4 bias4 = *(const float4*)(bout + o0 + tx * 4);
#pragma unroll
        for (int t = 0; t < 4; t++) {
            float2 lo = unpack2(acc2[t][0]);
            float2 hi = unpack2(acc2[t][1]);
            float4 r = make_float4(lo.x + bias4.x, lo.y + bias4.y,
                                   hi.x + bias4.z, hi.y + bias4.w);
            *(float4*)(ob + (long)(tok0 + t) * 512 + o0 + tx * 4) = r;
        }
        __syncthreads();
    }
}

// ---------------------------------------------------------------------------
// Launch: R12 structure, only fused_attn retiled.
// ---------------------------------------------------------------------------
extern "C" void kernel_launch(void* const* d_in, const int* in_sizes, int n_in,
                              void* d_out, int out_size) {
    const float* x    = (const float*)d_in[0];
    const float* ctx  = (const float*)d_in[1];
    const float* Wq   = (const float*)d_in[2];
    const float* Wk   = (const float*)d_in[3];
    const float* Wv   = (const float*)d_in[4];
    const float* We   = (const float*)d_in[5];
    const float* Wout = (const float*)d_in[6];
    const float* bout = (const float*)d_in[7];
    float* out = (float*)d_out;

    transpose512<<<dim3(16, 16), 256>>>(Wq);
    e0_kernel<<<B_, 512>>>(x, Wq, We);
    dist_topk_kernel<<<dim3(DIST_BLOCKS, B_), 256>>>(ctx);
    kvA_kernel<<<64, 1024>>>(ctx, Wk, Wv);
    kwB_kernel<<<dim3(8, 8), 512>>>(Wout);
    fused_attn<<<dim3(32, B_), 256>>>(x, out, bout);
}

// round 16
// speedup vs baseline: 2.1409x; 1.0237x over previous
#include <cuda_runtime.h>
#include <math.h>

// ---------------------------------------------------------------------------
// Problem constants
// ---------------------------------------------------------------------------
#define B_     8
#define N_     2048
#define M_     32768
#define QD_    512
#define DR_    256
#define D_     512
#define H_     8
#define DH_    64
#define INNER_ 512
#define TOPK_  8
#define SCALE_ 0.125f

#define DIST_BLOCKS 128
#define NCAND (DIST_BLOCKS * TOPK_)   // 1024
#define STR 68

// ---------------------------------------------------------------------------
// Scratch
// ---------------------------------------------------------------------------
__device__ float g_e0[B_ * DR_];
__device__ float g_cand_d2[B_ * NCAND];
__device__ int   g_cand_idx[B_ * NCAND];
__device__ int   g_topk_idx[B_ * TOPK_];
__device__ float g_WqT[QD_ * INNER_];     // WqT[i][p] = Wq[p][i]
__device__ float g_kappa[B_ * QD_ * 64];  // [b][p][c], c=j*8+h (SCALE folded)
__device__ float g_vw[B_ * 64 * INNER_];  // [b][c][o]
__device__ unsigned int g_done[B_];       // per-batch scan counter

// ---------------------------------------------------------------------------
// helpers
// ---------------------------------------------------------------------------
__device__ __forceinline__ unsigned long long splat2(float f) {
    unsigned long long r;
    asm("mov.b64 %0, {%1, %1};" : "=l"(r) : "f"(f));
    return r;
}
__device__ __forceinline__ void fma2(unsigned long long& d,
                                     unsigned long long a,
                                     unsigned long long b) {
    asm("fma.rn.f32x2 %0, %1, %2, %0;" : "+l"(d) : "l"(a), "l"(b));
}
__device__ __forceinline__ float2 unpack2(unsigned long long v) {
    float2 r;
    asm("mov.b64 {%0, %1}, %2;" : "=f"(r.x), "=f"(r.y) : "l"(v));
    return r;
}
__device__ __forceinline__ unsigned long long u64min(unsigned long long a,
                                                     unsigned long long b) {
    return a < b ? a : b;
}

// ---------------------------------------------------------------------------
// Kernel 0: transpose Wq -> g_WqT  (R12)
// ---------------------------------------------------------------------------
__global__ void transpose512(const float* __restrict__ Wq) {
    __shared__ float tile[32][33];
    int bx = blockIdx.x * 32, by = blockIdx.y * 32;
    int tx = threadIdx.x & 31, ty = threadIdx.x >> 5;
#pragma unroll
    for (int r = ty; r < 32; r += 8)
        tile[r][tx] = Wq[(by + r) * 512 + bx + tx];
    __syncthreads();
#pragma unroll
    for (int r = ty; r < 32; r += 8)
        g_WqT[(bx + r) * 512 + by + tx] = tile[tx][r];
}

// ---------------------------------------------------------------------------
// Kernel 1: e0  (R12)
// ---------------------------------------------------------------------------
__global__ void e0_kernel(const float* __restrict__ x,
                          const float* __restrict__ Wq,
                          const float* __restrict__ We) {
    int b = blockIdx.x;
    int tid = threadIdx.x;  // 512
    __shared__ float xs[QD_];
    __shared__ float q0[QD_];
    __shared__ float part[512];

    xs[tid] = x[(long)b * N_ * QD_ + tid];
    __syncthreads();

    {
        float acc = 0.f;
#pragma unroll 16
        for (int c = 0; c < QD_; c++)
            acc += xs[c] * Wq[c * INNER_ + tid];
        q0[tid] = acc;
    }
    __syncthreads();

    {
        int half = tid >> 8;
        int o = tid & 255;
        int c0 = half * 256;
        float acc = 0.f;
#pragma unroll 16
        for (int c = 0; c < 256; c++)
            acc += q0[c0 + c] * We[(c0 + c) * DR_ + o];
        part[tid] = acc;
    }
    __syncthreads();
    if (tid < DR_)
        g_e0[b * DR_ + tid] = part[tid] + part[tid + 256];
}

// ---------------------------------------------------------------------------
// Kernel 2: distance scan + local top-8 + LAST-BLOCK merge (R12)
// ---------------------------------------------------------------------------
__global__ void dist_topk_kernel(const float* __restrict__ ctx) {
    int b = blockIdx.y;
    int chunk = blockIdx.x;
    int tid = threadIdx.x;
    int warp = tid >> 5, lane = tid & 31;

    __shared__ float es[DR_];
    __shared__ float s_d2[8][TOPK_];
    __shared__ int   s_ix[8][TOPK_];
    __shared__ int   s_last;

    if (tid < DR_) es[tid] = g_e0[b * DR_ + tid];
    __syncthreads();

    const float4* e4 = (const float4*)es;
    float4 ea = e4[lane];
    float4 eb = e4[lane + 32];

    float best[TOPK_];
    int   bidx[TOPK_];
#pragma unroll
    for (int i = 0; i < TOPK_; i++) { best[i] = 3.0e38f; bidx[i] = -1; }

    int row0 = chunk * 256 + warp * 32;
#pragma unroll 2
    for (int r = 0; r < 32; r++) {
        int row = row0 + r;
        const float4* crow = (const float4*)(ctx + ((long)b * M_ + row) * D_);
        float4 ca = crow[lane];
        float4 cb = crow[lane + 32];
        float dx, d2 = 0.f;
        dx = ca.x - ea.x; d2 += dx * dx;
        dx = ca.y - ea.y; d2 += dx * dx;
        dx = ca.z - ea.z; d2 += dx * dx;
        dx = ca.w - ea.w; d2 += dx * dx;
        dx = cb.x - eb.x; d2 += dx * dx;
        dx = cb.y - eb.y; d2 += dx * dx;
        dx = cb.z - eb.z; d2 += dx * dx;
        dx = cb.w - eb.w; d2 += dx * dx;
#pragma unroll
        for (int off = 16; off; off >>= 1)
            d2 += __shfl_down_sync(0xffffffffu, d2, off);
        if (lane == 0 && d2 < best[TOPK_ - 1]) {
            int p = TOPK_ - 1;
            while (p > 0 && best[p - 1] > d2) {
                best[p] = best[p - 1]; bidx[p] = bidx[p - 1]; p--;
            }
            best[p] = d2; bidx[p] = row;
        }
    }

    if (lane == 0) {
#pragma unroll
        for (int i = 0; i < TOPK_; i++) { s_d2[warp][i] = best[i]; s_ix[warp][i] = bidx[i]; }
    }
    __syncthreads();

    if (tid == 0) {
        float fb[TOPK_]; int fi[TOPK_];
#pragma unroll
        for (int i = 0; i < TOPK_; i++) { fb[i] = 3.0e38f; fi[i] = -1; }
        for (int w = 0; w < 8; w++)
            for (int i = 0; i < TOPK_; i++) {
                float d2 = s_d2[w][i];
                if (d2 < fb[TOPK_ - 1]) {
                    int ix = s_ix[w][i];
                    int p = TOPK_ - 1;
                    while (p > 0 && fb[p - 1] > d2) {
                        fb[p] = fb[p - 1]; fi[p] = fi[p - 1]; p--;
                    }
                    fb[p] = d2; fi[p] = ix;
                }
            }
        int off = (b * DIST_BLOCKS + chunk) * TOPK_;
        for (int i = 0; i < TOPK_; i++) { g_cand_d2[off + i] = fb[i]; g_cand_idx[off + i] = fi[i]; }
        __threadfence();
        unsigned int v = atomicAdd(&g_done[b], 1u);
        s_last = (v == DIST_BLOCKS - 1);
    }
    __syncthreads();

    if (!s_last) return;
    __threadfence();  // acquire

    __shared__ unsigned long long warpmin[8];
    __shared__ unsigned long long winner;

    unsigned long long k[4];
    int base = b * NCAND;
#pragma unroll
    for (int s = 0; s < 4; s++) {
        int i = tid + s * 256;
        float d2 = g_cand_d2[base + i];
        int ix = g_cand_idx[base + i];
        k[s] = ((unsigned long long)__float_as_uint(d2) << 32) | (unsigned int)ix;
    }

    for (int sel = 0; sel < TOPK_; sel++) {
        unsigned long long m = u64min(u64min(k[0], k[1]), u64min(k[2], k[3]));
#pragma unroll
        for (int off = 16; off; off >>= 1)
            m = u64min(m, __shfl_down_sync(0xffffffffu, m, off));
        if (lane == 0) warpmin[warp] = m;
        __syncthreads();
        if (tid == 0) {
            unsigned long long w = warpmin[0];
#pragma unroll
            for (int i = 1; i < 8; i++) w = u64min(w, warpmin[i]);
            winner = w;
            g_topk_idx[b * TOPK_ + sel] = (int)(unsigned int)(w & 0xffffffffu);
        }
        __syncthreads();
        unsigned long long w = winner;
#pragma unroll
        for (int s = 0; s < 4; s++)
            if (k[s] == w) k[s] = ~0ULL;
        __syncthreads();
    }
    if (tid == 0) g_done[b] = 0;  // reset for graph replay
}

// ---------------------------------------------------------------------------
// Kernel 3: fused kv + kappa + vw, weights read once per (b,h).
// grid (8 h, 8 b) = 64 blocks, 512 thr.
//  phase B: thread (rq = tid>>7, kv = (tid>>6)&1, d = tid&63): 64-r split-K
//           partial k/v accumulation with 8-j register accumulators.
//  phase C: conflict-free padded-partials reduction -> kh/vh in smem.
//  phase D: kwB's kappa/vw (thread = p/o column, 8-j accumulators).
// ---------------------------------------------------------------------------
__global__ void __launch_bounds__(512)
kvkw2_kernel(const float* __restrict__ ctx,
             const float* __restrict__ Wk,
             const float* __restrict__ Wv,
             const float* __restrict__ Wout) {
    __shared__ float rows[8 * 512];     // 16 KB: [j][0:256)=reps, [256:512)=labels
    __shared__ float part[8 * 64 * 9];  // 18 KB: [(rq*2+kv)][d][j] padded to 9
    __shared__ float kh[8 * 64];        // [j][d]
    __shared__ float vh[8 * 64];        // [j][d]

    int h = blockIdx.x, b = blockIdx.y;
    int tid = threadIdx.x;  // 512

    // phase A: gather the 8 selected ctx rows
#pragma unroll
    for (int i = 0; i < 8; i++) {
        int f = tid + i * 512;           // 4096 floats
        int j = f >> 9, idx = f & 511;
        rows[j * 512 + idx] =
            ctx[((long)b * M_ + g_topk_idx[b * 8 + j]) * D_ + idx];
    }
    __syncthreads();

    // phase B: split-K partial k/v for head h
    {
        int d = tid & 63;
        int kv = (tid >> 6) & 1;         // 0 = K (labels@Wk), 1 = V (reps@Wv)
        int rq = tid >> 7;               // 0..3
        const float* W = kv ? Wv : Wk;
        int off = kv ? 0 : 256;
        int gcol = h * 64 + d;

        float acc[8];
#pragma unroll
        for (int j = 0; j < 8; j++) acc[j] = 0.f;
#pragma unroll 8
        for (int rr = 0; rr < 64; rr++) {
            int r = rq * 64 + rr;
            float w = W[r * INNER_ + gcol];
#pragma unroll
            for (int j = 0; j < 8; j++)
                acc[j] += rows[j * 512 + off + r] * w;
        }
        int base = ((rq * 2 + kv) * 64 + d) * 9;
#pragma unroll
        for (int j = 0; j < 8; j++) part[base + j] = acc[j];
    }
    __syncthreads();

    // phase C: reduce 4 rq partials -> kh/vh
#pragma unroll
    for (int s = 0; s < 2; s++) {
        int o = tid + s * 512;           // 0..1023 = kv*512 + d*8 + j
        int kv = o >> 9;
        int rem = o & 511;
        int d = rem >> 3, j = rem & 7;
        float sum = 0.f;
#pragma unroll
        for (int rq = 0; rq < 4; rq++)
            sum += part[((rq * 2 + kv) * 64 + d) * 9 + j];
        if (kv == 0) kh[j * 64 + d] = sum;
        else         vh[j * 64 + d] = sum;
    }
    __syncthreads();

    // phase D: kappa (thread = p) and vw (thread = o), as in kwB
    {
        float acc[8];
#pragma unroll
        for (int j = 0; j < 8; j++) acc[j] = 0.f;
#pragma unroll 8
        for (int d = 0; d < 64; d++) {
            float w = g_WqT[(h * 64 + d) * 512 + tid];
#pragma unroll
            for (int j = 0; j < 8; j++) acc[j] += w * kh[j * 64 + d];
        }
        long kbase = ((long)b * 512 + tid) * 64 + h;
#pragma unroll
        for (int j = 0; j < 8; j++) g_kappa[kbase + j * 8] = acc[j] * SCALE_;
    }
    {
        float acc[8];
#pragma unroll
        for (int j = 0; j < 8; j++) acc[j] = 0.f;
#pragma unroll 8
        for (int d = 0; d < 64; d++) {
            float w = Wout[(h * 64 + d) * 512 + tid];
#pragma unroll
            for (int j = 0; j < 8; j++) acc[j] += vh[j * 64 + d] * w;
        }
#pragma unroll
        for (int j = 0; j < 8; j++)
            g_vw[((long)b * 64 + j * 8 + h) * 512 + tid] = acc[j];
    }
}

// ---------------------------------------------------------------------------
// Kernel 4: fused sim + softmax + out. f32x2 over column pairs.
// grid (16, B), 256 thr, 128-token tile, single wave.  (identical to R12)
// ---------------------------------------------------------------------------
__global__ void __launch_bounds__(256)
fused_attn(const float* __restrict__ x,
           float* __restrict__ out,
           const float* __restrict__ bout) {
    extern __shared__ float fsm[];
    float* xs = fsm;              // 128*68
    float* ks = fsm + 128 * STR;  // 64*68

    int nc = blockIdx.x, b = blockIdx.y;
    int n0 = nc * 128;
    int tid = threadIdx.x;
    int ty = tid >> 4, tx = tid & 15;
    int tok0 = ty * 8;

    const float* xb = x + ((long)b * N_ + n0) * QD_;
    const float* kb = g_kappa + (long)b * QD_ * 64;

    unsigned long long acc2[8][2];
#pragma unroll
    for (int t = 0; t < 8; t++) { acc2[t][0] = 0ULL; acc2[t][1] = 0ULL; }

    for (int pc = 0; pc < 8; pc++) {
        int p0 = pc * 64;
#pragma unroll
        for (int l = 0; l < 8; l++) {
            int f = tid + l * 256;
            int row = f >> 4, c4 = (f & 15) * 4;
            *(float4*)&xs[row * STR + c4] =
                *(const float4*)(xb + (long)row * QD_ + p0 + c4);
        }
#pragma unroll
        for (int l = 0; l < 4; l++) {
            int f = tid + l * 256;
            int row = f >> 4, c4 = (f & 15) * 4;
            *(float4*)&ks[row * STR + c4] =
                *(const float4*)(kb + (long)(p0 + row) * 64 + c4);
        }
        __syncthreads();

#pragma unroll
        for (int kk4 = 0; kk4 < 64; kk4 += 4) {
            float4 a4[8];
#pragma unroll
            for (int t = 0; t < 8; t++)
                a4[t] = *(const float4*)&xs[(tok0 + t) * STR + kk4];
#pragma unroll
            for (int q = 0; q < 4; q++) {
                ulonglong2 bp = *(const ulonglong2*)&ks[(kk4 + q) * STR + tx * 4];
#pragma unroll
                for (int t = 0; t < 8; t++) {
                    unsigned long long av = splat2(((const float*)&a4[t])[q]);
                    fma2(acc2[t][0], av, bp.x);
                    fma2(acc2[t][1], av, bp.y);
                }
            }
        }
        __syncthreads();
    }

#pragma unroll
    for (int t = 0; t < 8; t++) {
        float2 lo = unpack2(acc2[t][0]);
        float2 hi = unpack2(acc2[t][1]);
        *(float4*)&xs[(tok0 + t) * STR + tx * 4] =
            make_float4(lo.x, lo.y, hi.x, hi.y);
    }
    __syncthreads();

#pragma unroll
    for (int s = 0; s < 4; s++) {
        int task = s * 256 + tid;
        int t = task >> 3, h = task & 7;
        float v[8];
#pragma unroll
        for (int j = 0; j < 8; j++) v[j] = xs[t * STR + j * 8 + h];
        float m = v[0];
#pragma unroll
        for (int j = 1; j < 8; j++) m = fmaxf(m, v[j]);
        float e[8], sum = 0.f;
#pragma unroll
        for (int j = 0; j < 8; j++) { e[j] = __expf(v[j] - m); sum += e[j]; }
        float inv = 1.f / sum;
#pragma unroll
        for (int j = 0; j < 8; j++) xs[t * STR + j * 8 + h] = e[j] * inv;
    }
    __syncthreads();

    const float* vwb = g_vw + (long)b * 64 * 512;
    float* ob = out + ((long)b * N_ + n0) * 512;

    for (int oc = 0; oc < 8; oc++) {
        int o0 = oc * 64;
#pragma unroll
        for (int l = 0; l < 4; l++) {
            int f = tid + l * 256;
            int row = f >> 4, c4 = (f & 15) * 4;
            *(float4*)&ks[row * STR + c4] =
                *(const float4*)(vwb + (long)row * 512 + o0 + c4);
        }
#pragma unroll
        for (int t = 0; t < 8; t++) { acc2[t][0] = 0ULL; acc2[t][1] = 0ULL; }
        __syncthreads();

#pragma unroll
        for (int cc4 = 0; cc4 < 64; cc4 += 4) {
            float4 a4[8];
#pragma unroll
            for (int t = 0; t < 8; t++)
                a4[t] = *(const float4*)&xs[(tok0 + t) * STR + cc4];
#pragma unroll
            for (int q = 0; q < 4; q++) {
                ulonglong2 bp = *(const ulonglong2*)&ks[(cc4 + q) * STR + tx * 4];
#pragma unroll
                for (int t = 0; t < 8; t++) {
                    unsigned long long av = splat2(((const float*)&a4[t])[q]);
                    fma2(acc2[t][0], av, bp.x);
                    fma2(acc2[t][1], av, bp.y);
                }
            }
        }

        float4 bias4 = *(const float4*)(bout + o0 + tx * 4);
#pragma unroll
        for (int t = 0; t < 8; t++) {
            float2 lo = unpack2(acc2[t][0]);
            float2 hi = unpack2(acc2[t][1]);
            float4 r = make_float4(lo.x + bias4.x, lo.y + bias4.y,
                                   hi.x + bias4.z, hi.y + bias4.w);
            *(float4*)(ob + (long)(tok0 + t) * 512 + o0 + tx * 4) = r;
        }
        __syncthreads();
    }
}

// ---------------------------------------------------------------------------
// Launch: 5 kernels (R12 minus one: kvA+kwB -> kvkw2).
// ---------------------------------------------------------------------------
extern "C" void kernel_launch(void* const* d_in, const int* in_sizes, int n_in,
                              void* d_out, int out_size) {
    const float* x    = (const float*)d_in[0];
    const float* ctx  = (const float*)d_in[1];
    const float* Wq   = (const float*)d_in[2];
    const float* Wk   = (const float*)d_in[3];
    const float* Wv   = (const float*)d_in[4];
    const float* We   = (const float*)d_in[5];
    const float* Wout = (const float*)d_in[6];
    const float* bout = (const float*)d_in[7];
    float* out = (float*)d_out;

    const int FA_SMEM = (128 * STR + 64 * STR) * sizeof(float);  // ~51 KB
    cudaFuncSetAttribute(fused_attn,
                         cudaFuncAttributeMaxDynamicSharedMemorySize, FA_SMEM);

    transpose512<<<dim3(16, 16), 256>>>(Wq);
    e0_kernel<<<B_, 512>>>(x, Wq, We);
    dist_topk_kernel<<<dim3(DIST_BLOCKS, B_), 256>>>(ctx);
    kvkw2_kernel<<<dim3(8, 8), 512>>>(ctx, Wk, Wv, Wout);
    fused_attn<<<dim3(16, B_), 256, FA_SMEM>>>(x, out, bout);
}